// round 3
// baseline (speedup 1.0000x reference)
#include <cuda_runtime.h>

#define NN 16384
#define CC 64
#define JJ 16
#define OO 128
#define PSTR 36   // proj row stride in floats (144B, 16B-aligned; mod-32 banks = 4)

// Transposed weight: [j][c][o], o contiguous -> coalesced LDG.64 per lane.
__device__ float g_Wt[JJ * CC * OO];

__global__ void wt_transpose_kernel(const float* __restrict__ w) {
    int i = blockIdx.x * 256 + threadIdx.x;   // 131072 total
    int j = i >> 13;
    int c = (i >> 7) & 63;
    int o = i & 127;
    g_Wt[i] = w[(o * CC + c) * JJ + j];
}

__device__ __forceinline__ void ffma2(unsigned long long& a, unsigned long long x, unsigned long long y) {
    asm("fma.rn.f32x2 %0, %1, %2, %0;" : "+l"(a) : "l"(x), "l"(y));
}
__device__ __forceinline__ unsigned long long pk2(float lo, float hi) {
    unsigned long long r; asm("mov.b64 %0, {%1, %2};" : "=l"(r) : "f"(lo), "f"(hi)); return r;
}
__device__ __forceinline__ float2 up2(unsigned long long v) {
    float2 r; asm("mov.b64 {%0, %1}, %2;" : "=f"(r.x), "=f"(r.y) : "l"(v)); return r;
}

__global__ __launch_bounds__(128, 5) void sconv_kernel(
    const float* __restrict__ x, const int* __restrict__ adj, float* __restrict__ out)
{
    __shared__ __align__(16) float proj[2][CC * PSTR];   // double-buffered [c][p]
    __shared__ int adjS[32 * JJ];

    const int tid = threadIdx.x;
    const int bx = blockIdx.x;
    const int b  = bx >> 9;                 // 512 blocks per batch
    const int n0 = (bx & 511) << 5;         // 32 points per block
    const float* xb = x + ((size_t)b * NN) * CC;

    // stage-1 mapping: 4 lanes per point, 16 channels per lane
    const int p_ = tid >> 2;
    const int l  = tid & 3;
    const int c0 = l << 4;
    // stage-2 mapping (R1's): 2 outs x 16 points per thread
    const int ph = tid >> 6;                // point-half (16 points)
    const int o0 = (tid & 63) << 1;         // 2 output channels

    // ---- adjacency preload (skip self column 0) ----
    {
        int base = (b * NN + n0) * 17;
        #pragma unroll
        for (int i = 0; i < 4; i++) {
            int idx = tid + 128 * i;          // 512 ints
            int p = idx >> 4, jj = idx & 15;
            adjS[idx] = adj[base + p * 17 + 1 + jj];
        }
    }

    // ---- center values in registers for all j (no conflicted smem reads) ----
    float ce[16];
    {
        const float4* cp = (const float4*)(xb + (n0 + p_) * CC + c0);
        #pragma unroll
        for (int q = 0; q < 4; q++) {
            float4 v = cp[q];
            ce[4*q+0] = v.x; ce[4*q+1] = v.y; ce[4*q+2] = v.z; ce[4*q+3] = v.w;
        }
    }
    __syncthreads();   // adjS ready

    auto stage1 = [&](int jj) {
        int g = adjS[p_ * JJ + jj];
        const float4* nb = (const float4*)(xb + (size_t)g * CC) + l * 4;
        float d[16];
        float ssq = 0.f;
        #pragma unroll
        for (int q = 0; q < 4; q++) {
            float4 nv = nb[q];
            d[4*q+0] = nv.x - ce[4*q+0]; d[4*q+1] = nv.y - ce[4*q+1];
            d[4*q+2] = nv.z - ce[4*q+2]; d[4*q+3] = nv.w - ce[4*q+3];
        }
        #pragma unroll
        for (int q = 0; q < 16; q++) ssq = fmaf(d[q], d[q], ssq);
        ssq += __shfl_xor_sync(0xffffffffu, ssq, 1);
        ssq += __shfl_xor_sync(0xffffffffu, ssq, 2);
        float s = rsqrtf(2.0f * ssq);   // 1/(sqrt2 * ||diff||)
        float* pr = proj[jj & 1];
        #pragma unroll
        for (int qq = 0; qq < 16; qq++) {
            int q = (qq + 4 * l) & 15;   // rotation: 4-way -> 2-way store conflicts
            pr[(c0 + q) * PSTR + p_] = d[q] * s;
        }
    };

    float m[32];
    #pragma unroll
    for (int i = 0; i < 32; i++) m[i] = 0.0f;   // relu+max -> init 0

    stage1(0);
    __syncthreads();

    for (int j = 0; j < JJ; j++) {
        // ---- stage 2: 2x16 register tile, f32x2 packed ----
        unsigned long long acc[16];
        #pragma unroll
        for (int i = 0; i < 16; i++) acc[i] = 0ULL;

        const float2* Wj = (const float2*)(g_Wt + j * (CC * OO)) + (o0 >> 1);
        const float* pbuf = proj[j & 1];
        #pragma unroll 4
        for (int c = 0; c < CC; c++) {
            float2 w = Wj[c * 64];                       // coalesced LDG.64 (L1-hit)
            unsigned long long w0 = pk2(w.x, w.x);
            unsigned long long w1 = pk2(w.y, w.y);
            const ulonglong2* r = (const ulonglong2*)(pbuf + c * PSTR) + ph * 4;
            ulonglong2 u0 = r[0], u1 = r[1], u2 = r[2], u3 = r[3];  // broadcast LDS.128
            ffma2(acc[0],  w0, u0.x); ffma2(acc[1],  w0, u0.y);
            ffma2(acc[2],  w0, u1.x); ffma2(acc[3],  w0, u1.y);
            ffma2(acc[4],  w0, u2.x); ffma2(acc[5],  w0, u2.y);
            ffma2(acc[6],  w0, u3.x); ffma2(acc[7],  w0, u3.y);
            ffma2(acc[8],  w1, u0.x); ffma2(acc[9],  w1, u0.y);
            ffma2(acc[10], w1, u1.x); ffma2(acc[11], w1, u1.y);
            ffma2(acc[12], w1, u2.x); ffma2(acc[13], w1, u2.y);
            ffma2(acc[14], w1, u3.x); ffma2(acc[15], w1, u3.y);
        }
        #pragma unroll
        for (int i = 0; i < 16; i++) {
            float2 v = up2(acc[i]);
            int to = i >> 3, k = i & 7;
            m[to * 16 + 2 * k]     = fmaxf(m[to * 16 + 2 * k],     v.x);
            m[to * 16 + 2 * k + 1] = fmaxf(m[to * 16 + 2 * k + 1], v.y);
        }

        // ---- stage 1 for j+1 into the other buffer (overlaps with next stage-2 warps) ----
        if (j + 1 < JJ) stage1(j + 1);
        __syncthreads();
    }

    // ---- write out[b][o][n]: 2 rows x 16 consecutive n per thread ----
    float* op = out + ((size_t)(b * OO + o0) * NN) + n0 + ph * 16;
    #pragma unroll
    for (int to = 0; to < 2; to++) {
        float4* v = (float4*)(op + (size_t)to * NN);
        #pragma unroll
        for (int q = 0; q < 4; q++)
            v[q] = make_float4(m[to*16 + 4*q], m[to*16 + 4*q + 1],
                               m[to*16 + 4*q + 2], m[to*16 + 4*q + 3]);
    }
}

extern "C" void kernel_launch(void* const* d_in, const int* in_sizes, int n_in,
                              void* d_out, int out_size) {
    const float* x   = (const float*)d_in[0];
    const int*   adj = (const int*)d_in[1];
    const float* w   = (const float*)d_in[2];
    float* out = (float*)d_out;

    wt_transpose_kernel<<<512, 256>>>(w);       // trivial; same stream -> ordered
    sconv_kernel<<<1024, 128>>>(x, adj, out);
}

// round 5
// speedup vs baseline: 2.6851x; 2.6851x over previous
#include <cuda_runtime.h>
#include <cuda_bf16.h>
#include <cstdint>

#define NN 16384
#define CC 64
#define JJ 16
#define OO 128
#define PTS 128
#define RS 272                 // smem row stride bytes (256 data + 16 pad; 68 words -> conflict-free ldmatrix)
#define WJB (OO * 256)         // 32768 compact bytes per j: [o][hi64|lo64] bf16

// smem layout (bytes)
#define SM_ADJ 0
#define SM_W   8192                    // 2 x 34816
#define SM_P   (8192 + 2*34816)        // 77824; 2 x 34816
#define SM_STG (77824 + 2*34816)       // 147456; 1 x 34816 (cp.async gather staging)
#define SMEMTOT (147456 + 34816)       // 182272

__device__ unsigned char g_W[JJ * WJB];

// g_W[j][o][k2], k2<64: bf16 hi of w; k2>=64: bf16 lo residual
__global__ void wprep(const float* __restrict__ w) {
    int i = blockIdx.x * 256 + threadIdx.x;     // 16*128*128 = 262144
    int k2 = i & 127;
    int o  = (i >> 7) & 127;
    int j  = i >> 14;
    int c  = k2 & 63;
    float v = w[(o * CC + c) * JJ + j];
    __nv_bfloat16 hb = __float2bfloat16_rn(v);
    unsigned short bits = (k2 < 64) ? __bfloat16_as_ushort(hb)
        : __bfloat16_as_ushort(__float2bfloat16_rn(v - __bfloat162float(hb)));
    *(unsigned short*)(g_W + (size_t)j * WJB + o * 256 + k2 * 2) = bits;
}

__device__ __forceinline__ uint32_t smem_u32(const void* p) {
    uint32_t a; asm("{ .reg .u64 t; cvta.to.shared.u64 t, %1; cvt.u32.u64 %0, t; }" : "=r"(a) : "l"(p));
    return a;
}
__device__ __forceinline__ uint32_t pkbf(float flo, float fhi) {   // low half <- flo
    uint32_t r; asm("cvt.rn.bf16x2.f32 %0, %1, %2;" : "=r"(r) : "f"(fhi), "f"(flo));
    return r;
}
__device__ __forceinline__ void ldm4(uint32_t* r, uint32_t addr) {
    asm volatile("ldmatrix.sync.aligned.m8n8.x4.shared.b16 {%0,%1,%2,%3}, [%4];"
        : "=r"(r[0]), "=r"(r[1]), "=r"(r[2]), "=r"(r[3]) : "r"(addr));
}
__device__ __forceinline__ void mma16816(float* c, const uint32_t* a, uint32_t b0, uint32_t b1) {
    asm volatile("mma.sync.aligned.m16n8k16.row.col.f32.bf16.bf16.f32 "
        "{%0,%1,%2,%3},{%4,%5,%6,%7},{%8,%9},{%0,%1,%2,%3};"
        : "+f"(c[0]), "+f"(c[1]), "+f"(c[2]), "+f"(c[3])
        : "r"(a[0]), "r"(a[1]), "r"(a[2]), "r"(a[3]), "r"(b0), "r"(b1));
}
__device__ __forceinline__ void cp16(uint32_t dst, const void* src) {
    asm volatile("cp.async.cg.shared.global [%0], [%1], 16;" :: "r"(dst), "l"(src));
}

__global__ __launch_bounds__(256) void sconv_kernel(
    const float* __restrict__ x, const int* __restrict__ adj, float* __restrict__ out)
{
    extern __shared__ unsigned char S[];
    const uint32_t sb = smem_u32(S);
    const int tid = threadIdx.x, lid = tid & 31, wid = tid >> 5;
    const int b  = blockIdx.x >> 7;
    const int n0 = (blockIdx.x & 127) << 7;       // 128 points per block
    const float* xb = x + (size_t)b * NN * CC;

    int* adjS = (int*)S;
    {
        int base = (b * NN + n0) * 17;
        #pragma unroll
        for (int i = 0; i < 8; i++) {
            int idx = tid + 256 * i;              // 2048 ints (skip self col 0)
            adjS[idx] = adj[base + (idx >> 4) * 17 + 1 + (idx & 15)];
        }
    }
    __syncthreads();

    const int p_ = tid >> 1, lch = tid & 1;       // 2 lanes/point, 32 channels each

    auto gatherA = [&](int j) {                   // neighbor row -> staging (async)
        int g = adjS[p_ * 16 + j];
        const float* src = xb + (size_t)g * CC + lch * 32;
        uint32_t dst = sb + SM_STG + p_ * RS + lch * 128;
        #pragma unroll
        for (int q = 0; q < 8; q++) cp16(dst + q * 16, src + q * 4);
    };
    auto copyW = [&](int j) {                     // weights -> smem (async)
        const unsigned char* src = g_W + (size_t)j * WJB;
        uint32_t dst = sb + SM_W + (j & 1) * 34816;
        #pragma unroll
        for (int i = 0; i < 8; i++) {
            int idx = tid + 256 * i;              // 2048 x 16B
            cp16(dst + (idx >> 4) * RS + (idx & 15) * 16, src + (size_t)idx * 16);
        }
    };
    auto buildP = [&](int j) {                    // staged neighbor -> split-bf16 proj row
        const float4* st = (const float4*)(S + SM_STG + p_ * RS + lch * 128);
        const float4* cp_ = (const float4*)(xb + (size_t)(n0 + p_) * CC + lch * 32);
        float d[32]; float ssq = 0.f;
        #pragma unroll
        for (int q = 0; q < 8; q++) {
            float4 nv = st[q], cv = cp_[q];
            d[4*q+0] = nv.x - cv.x; d[4*q+1] = nv.y - cv.y;
            d[4*q+2] = nv.z - cv.z; d[4*q+3] = nv.w - cv.w;
        }
        #pragma unroll
        for (int q = 0; q < 32; q++) ssq = fmaf(d[q], d[q], ssq);
        ssq += __shfl_xor_sync(0xffffffffu, ssq, 1);
        float s = rsqrtf(2.0f * ssq);             // 1/(sqrt2*||diff||)
        uint32_t h[16], lo[16];
        #pragma unroll
        for (int q = 0; q < 16; q++) {
            float e = d[2*q] * s, od = d[2*q+1] * s;
            h[q] = pkbf(e, od);
            float hl = __uint_as_float(h[q] << 16);
            float hh = __uint_as_float(h[q] & 0xFFFF0000u);
            lo[q] = pkbf(e - hl, od - hh);
        }
        unsigned char* P = S + SM_P + (j & 1) * 34816 + p_ * RS + lch * 64;
        #pragma unroll
        for (int q = 0; q < 4; q++) ((uint4*)P)[q] = ((uint4*)h)[q];          // hi seg
        #pragma unroll
        for (int q = 0; q < 4; q++) ((uint4*)(P + 128))[q] = ((uint4*)lo)[q]; // lo seg
    };

    // warp tiles: 4 m-warps x 2 n-warps; per warp m32 x n64
    const int m0 = (wid & 3) * 32;
    const int nw = (wid >> 2) * 64;
    const int g8 = lid >> 3, r8 = lid & 7;
    const uint32_t aoff = (uint32_t)((m0 + r8 + 8 * (g8 & 1)) * RS + (g8 >> 1) * 16);
    const uint32_t boff = (uint32_t)((nw + r8 + 8 * (g8 >> 1)) * RS + (g8 & 1) * 16);

    float acc[64], mx[64];
    #pragma unroll
    for (int i = 0; i < 64; i++) mx[i] = 0.f;     // relu+max -> init 0

    // prologue
    copyW(0); gatherA(0);
    asm volatile("cp.async.commit_group;");
    asm volatile("cp.async.wait_group 0;" ::: "memory");
    buildP(0);
    __syncthreads();

    // per-kstep byte offsets realizing (hi,hi),(hi,lo),(lo,hi) over K=64 each
    const int ksA[12] = {0,32,64,96,   0,32,64,96, 128,160,192,224};
    const int ksB[12] = {0,32,64,96, 128,160,192,224, 0,32,64,96};

    for (int j = 0; j < JJ; j++) {
        if (j + 1 < JJ) {
            gatherA(j + 1);
            copyW(j + 1);
            asm volatile("cp.async.commit_group;");
        }
        #pragma unroll
        for (int i = 0; i < 64; i++) acc[i] = 0.f;
        const uint32_t Wb = sb + SM_W + (j & 1) * 34816;
        const uint32_t Pb = sb + SM_P + (j & 1) * 34816;
        #pragma unroll
        for (int kc = 0; kc < 12; kc++) {
            uint32_t a0[4], a1[4], bb[4][4];
            ldm4(a0, Wb + aoff + ksA[kc]);
            ldm4(a1, Wb + aoff + 16 * RS + ksA[kc]);
            #pragma unroll
            for (int q = 0; q < 4; q++) ldm4(bb[q], Pb + boff + 16 * q * RS + ksB[kc]);
            #pragma unroll
            for (int q = 0; q < 4; q++) {
                #pragma unroll
                for (int h2 = 0; h2 < 2; h2++) {
                    int nt = 2 * q + h2;
                    mma16816(&acc[nt * 4],      a0, bb[q][2*h2], bb[q][2*h2+1]);
                    mma16816(&acc[32 + nt * 4], a1, bb[q][2*h2], bb[q][2*h2+1]);
                }
            }
        }
        #pragma unroll
        for (int i = 0; i < 64; i++) mx[i] = fmaxf(mx[i], acc[i]);

        if (j + 1 < JJ) {
            asm volatile("cp.async.wait_group 0;" ::: "memory");
            buildP(j + 1);
        }
        __syncthreads();
    }

    // write out[b][o][n]
    {
        const int r4 = lid >> 2, c4 = lid & 3;
        #pragma unroll
        for (int mi = 0; mi < 2; mi++) {
            #pragma unroll
            for (int nt = 0; nt < 8; nt++) {
                float* a = &mx[mi * 32 + nt * 4];
                int ncol = n0 + nw + nt * 8 + 2 * c4;
                int o1 = m0 + 16 * mi + r4;
                *(float2*)(out + (size_t)(b * OO + o1) * NN + ncol)     = make_float2(a[0], a[1]);
                *(float2*)(out + (size_t)(b * OO + o1 + 8) * NN + ncol) = make_float2(a[2], a[3]);
            }
        }
    }
}

extern "C" void kernel_launch(void* const* d_in, const int* in_sizes, int n_in,
                              void* d_out, int out_size) {
    const float* x   = (const float*)d_in[0];
    const int*   adj = (const int*)d_in[1];
    const float* w   = (const float*)d_in[2];
    float* out = (float*)d_out;

    cudaFuncSetAttribute(sconv_kernel, cudaFuncAttributeMaxDynamicSharedMemorySize, SMEMTOT);
    wprep<<<1024, 256>>>(w);
    sconv_kernel<<<256, 256, SMEMTOT>>>(x, adj, out);
}

// round 6
// speedup vs baseline: 2.9833x; 1.1111x over previous
#include <cuda_runtime.h>
#include <cuda_bf16.h>
#include <cstdint>

#define NN 16384
#define CC 64
#define JJ 16
#define OO 128
#define PTS 128
#define RS 272                 // smem row stride bytes (256 data + 16 pad)
#define WJB (OO * 256)         // 32768 compact bytes per j: [o][hi64|lo64] bf16

// smem layout (bytes)
#define SM_ADJ 0
#define SM_W   8192                    // 2 x 34816
#define SM_P   (8192 + 2*34816)        // 77824; 2 x 34816
#define SM_STG (77824 + 2*34816)       // 147456; 1 x 34816
#define SMEMTOT (147456 + 34816)       // 182272

__device__ unsigned char g_W[JJ * WJB];

__global__ void wprep(const float* __restrict__ w) {
    int i = blockIdx.x * 256 + threadIdx.x;     // 262144
    int k2 = i & 127;
    int o  = (i >> 7) & 127;
    int j  = i >> 14;
    int c  = k2 & 63;
    float v = w[(o * CC + c) * JJ + j];
    __nv_bfloat16 hb = __float2bfloat16_rn(v);
    unsigned short bits = (k2 < 64) ? __bfloat16_as_ushort(hb)
        : __bfloat16_as_ushort(__float2bfloat16_rn(v - __bfloat162float(hb)));
    *(unsigned short*)(g_W + (size_t)j * WJB + o * 256 + k2 * 2) = bits;
}

__device__ __forceinline__ uint32_t smem_u32(const void* p) {
    uint32_t a; asm("{ .reg .u64 t; cvta.to.shared.u64 t, %1; cvt.u32.u64 %0, t; }" : "=r"(a) : "l"(p));
    return a;
}
__device__ __forceinline__ uint32_t pkbf(float flo, float fhi) {
    uint32_t r; asm("cvt.rn.bf16x2.f32 %0, %1, %2;" : "=r"(r) : "f"(fhi), "f"(flo));
    return r;
}
__device__ __forceinline__ void ldm4(uint32_t* r, uint32_t addr) {
    asm volatile("ldmatrix.sync.aligned.m8n8.x4.shared.b16 {%0,%1,%2,%3}, [%4];"
        : "=r"(r[0]), "=r"(r[1]), "=r"(r[2]), "=r"(r[3]) : "r"(addr));
}
__device__ __forceinline__ void mma16816(float* c, const uint32_t* a, uint32_t b0, uint32_t b1) {
    asm volatile("mma.sync.aligned.m16n8k16.row.col.f32.bf16.bf16.f32 "
        "{%0,%1,%2,%3},{%4,%5,%6,%7},{%8,%9},{%0,%1,%2,%3};"
        : "+f"(c[0]), "+f"(c[1]), "+f"(c[2]), "+f"(c[3])
        : "r"(a[0]), "r"(a[1]), "r"(a[2]), "r"(a[3]), "r"(b0), "r"(b1));
}
__device__ __forceinline__ void cp16(uint32_t dst, const void* src) {
    asm volatile("cp.async.cg.shared.global [%0], [%1], 16;" :: "r"(dst), "l"(src));
}

__global__ __launch_bounds__(512, 1) void sconv_kernel(
    const float* __restrict__ x, const int* __restrict__ adj, float* __restrict__ out)
{
    extern __shared__ unsigned char S[];
    const uint32_t sb = smem_u32(S);
    const int tid = threadIdx.x, lid = tid & 31, wid = tid >> 5;
    const int b  = blockIdx.x >> 7;
    const int n0 = (blockIdx.x & 127) << 7;       // 128 points per block
    const float* xb = x + (size_t)b * NN * CC;

    int* adjS = (int*)S;
    {
        int base = (b * NN + n0) * 17;
        #pragma unroll
        for (int i = 0; i < 4; i++) {
            int idx = tid + 512 * i;              // 2048 ints (skip self col 0)
            adjS[idx] = adj[base + (idx >> 4) * 17 + 1 + (idx & 15)];
        }
    }
    __syncthreads();

    const int p_ = tid >> 2, l = tid & 3;         // 4 lanes/point, 16 channels each

    auto gatherA = [&](int j) {                   // neighbor row -> staging (async)
        int g = adjS[p_ * 16 + j];
        const float* src = xb + (size_t)g * CC + l * 16;
        uint32_t dst = sb + SM_STG + p_ * RS + l * 64;
        #pragma unroll
        for (int q = 0; q < 4; q++) cp16(dst + q * 16, src + q * 4);
    };
    auto copyW = [&](int j) {                     // weights -> smem (async)
        const unsigned char* src = g_W + (size_t)j * WJB;
        uint32_t dst = sb + SM_W + (j & 1) * 34816;
        #pragma unroll
        for (int i = 0; i < 4; i++) {
            int idx = tid + 512 * i;              // 2048 x 16B
            cp16(dst + (idx >> 4) * RS + (idx & 15) * 16, src + (size_t)idx * 16);
        }
    };
    auto buildP = [&](int j) {                    // staged neighbor -> split-bf16 proj row
        const float4* st = (const float4*)(S + SM_STG + p_ * RS + l * 64);
        const float4* cp_ = (const float4*)(xb + (size_t)(n0 + p_) * CC + l * 16);
        float d[16]; float ssq = 0.f;
        #pragma unroll
        for (int q = 0; q < 4; q++) {
            float4 nv = st[q], cv = cp_[q];
            d[4*q+0] = nv.x - cv.x; d[4*q+1] = nv.y - cv.y;
            d[4*q+2] = nv.z - cv.z; d[4*q+3] = nv.w - cv.w;
        }
        #pragma unroll
        for (int q = 0; q < 16; q++) ssq = fmaf(d[q], d[q], ssq);
        ssq += __shfl_xor_sync(0xffffffffu, ssq, 1);
        ssq += __shfl_xor_sync(0xffffffffu, ssq, 2);
        float s = rsqrtf(2.0f * ssq);             // 1/(sqrt2*||diff||)
        uint32_t h[8], lo[8];
        #pragma unroll
        for (int q = 0; q < 8; q++) {
            float e = d[2*q] * s, od = d[2*q+1] * s;
            h[q] = pkbf(e, od);
            float hl = __uint_as_float(h[q] << 16);
            float hh = __uint_as_float(h[q] & 0xFFFF0000u);
            lo[q] = pkbf(e - hl, od - hh);
        }
        unsigned char* P = S + SM_P + (j & 1) * 34816 + p_ * RS + l * 32;
        ((uint4*)P)[0] = ((uint4*)h)[0];  ((uint4*)P)[1] = ((uint4*)h)[1];          // hi
        ((uint4*)(P + 128))[0] = ((uint4*)lo)[0]; ((uint4*)(P + 128))[1] = ((uint4*)lo)[1]; // lo
    };

    // warp tiles: 4 m-warps x 4 n-warps; per warp m32 x n32
    const int m0 = (wid & 3) * 32;
    const int nw = (wid >> 2) * 32;
    const int g8 = lid >> 3, r8 = lid & 7;
    const uint32_t aoff = (uint32_t)((m0 + r8 + 8 * (g8 & 1)) * RS + (g8 >> 1) * 16);
    const uint32_t boff = (uint32_t)((nw + r8 + 8 * (g8 >> 1)) * RS + (g8 & 1) * 16);

    float acc[32], mx[32];
    #pragma unroll
    for (int i = 0; i < 32; i++) mx[i] = 0.f;     // relu+max -> init 0

    // prologue
    copyW(0); gatherA(0);
    asm volatile("cp.async.commit_group;");
    asm volatile("cp.async.wait_group 0;" ::: "memory");
    buildP(0);
    __syncthreads();

    // per-kstep byte offsets realizing (hi,hi),(hi,lo),(lo,hi) over K=64 each
    const int ksA[12] = {0,32,64,96,   0,32,64,96, 128,160,192,224};
    const int ksB[12] = {0,32,64,96, 128,160,192,224, 0,32,64,96};

    for (int j = 0; j < JJ; j++) {
        if (j + 1 < JJ) {
            gatherA(j + 1);
            copyW(j + 1);
            asm volatile("cp.async.commit_group;");
        }
        #pragma unroll
        for (int i = 0; i < 32; i++) acc[i] = 0.f;
        const uint32_t Wb = sb + SM_W + (j & 1) * 34816;
        const uint32_t Pb = sb + SM_P + (j & 1) * 34816;
        #pragma unroll
        for (int kc = 0; kc < 12; kc++) {
            uint32_t a0[4], a1[4], bb[2][4];
            ldm4(a0, Wb + aoff + ksA[kc]);
            ldm4(a1, Wb + aoff + 16 * RS + ksA[kc]);
            #pragma unroll
            for (int q = 0; q < 2; q++) ldm4(bb[q], Pb + boff + 16 * q * RS + ksB[kc]);
            #pragma unroll
            for (int q = 0; q < 2; q++) {
                #pragma unroll
                for (int h2 = 0; h2 < 2; h2++) {
                    int nt = 2 * q + h2;
                    mma16816(&acc[nt * 4],      a0, bb[q][2*h2], bb[q][2*h2+1]);
                    mma16816(&acc[16 + nt * 4], a1, bb[q][2*h2], bb[q][2*h2+1]);
                }
            }
        }
        #pragma unroll
        for (int i = 0; i < 32; i++) mx[i] = fmaxf(mx[i], acc[i]);

        if (j + 1 < JJ) {
            asm volatile("cp.async.wait_group 0;" ::: "memory");
            buildP(j + 1);
        }
        __syncthreads();
    }

    // write out[b][o][n]
    {
        const int r4 = lid >> 2, c4 = lid & 3;
        #pragma unroll
        for (int mi = 0; mi < 2; mi++) {
            #pragma unroll
            for (int nt = 0; nt < 4; nt++) {
                float* a = &mx[mi * 16 + nt * 4];
                int ncol = n0 + nw + nt * 8 + 2 * c4;
                int o1 = m0 + 16 * mi + r4;
                *(float2*)(out + (size_t)(b * OO + o1) * NN + ncol)     = make_float2(a[0], a[1]);
                *(float2*)(out + (size_t)(b * OO + o1 + 8) * NN + ncol) = make_float2(a[2], a[3]);
            }
        }
    }
}

extern "C" void kernel_launch(void* const* d_in, const int* in_sizes, int n_in,
                              void* d_out, int out_size) {
    const float* x   = (const float*)d_in[0];
    const int*   adj = (const int*)d_in[1];
    const float* w   = (const float*)d_in[2];
    float* out = (float*)d_out;

    cudaFuncSetAttribute(sconv_kernel, cudaFuncAttributeMaxDynamicSharedMemorySize, SMEMTOT);
    wprep<<<1024, 256>>>(w);
    sconv_kernel<<<256, 512, SMEMTOT>>>(x, adj, out);
}

// round 7
// speedup vs baseline: 3.7240x; 1.2483x over previous
#include <cuda_runtime.h>
#include <cuda_bf16.h>
#include <cstdint>

#define NN 16384
#define CC 64
#define JJ 16
#define OO 128
#define PTS 128
#define RS 272                 // proj smem row stride bytes (256 data + 16 pad)

// smem layout (bytes)
#define SM_ADJ 0                       // 8192
#define SM_P   8192                    // 2 x 34816
#define SM_STG (8192 + 2*34816)        // 77824; 34816 gather staging
#define SMEMTOT (77824 + 34816)        // 112640

// W pre-baked in mma-fragment layout:
// byte addr = (((j*4+chunk)*2+seg)*4 + mi)*1024 + half*512 + lane*16 + word*4
// seg: 0=hi bf16, 1=lo residual; half: m-rows +0 / +16 within the warp tile
__device__ unsigned char g_Wfrag[JJ * 4 * 2 * 4 * 1024];   // 512 KB

__global__ void wprep(const float* __restrict__ w) {
    int i = blockIdx.x * 256 + threadIdx.x;      // 131072 words
    int wrd  = i & 3;
    int lane = (i >> 2) & 31;
    int half = (i >> 7) & 1;
    int mi   = (i >> 8) & 3;
    int seg  = (i >> 10) & 1;
    int chunk= (i >> 11) & 3;
    int j    = i >> 13;
    int o = mi * 32 + half * 16 + (wrd & 1) * 8 + (lane >> 2);
    int k = chunk * 16 + ((wrd >> 1) & 1) * 8 + 2 * (lane & 3);
    float v0 = w[(o * CC + k) * JJ + j];
    float v1 = w[(o * CC + k + 1) * JJ + j];
    unsigned short b0, b1;
    if (seg == 0) {
        b0 = __bfloat16_as_ushort(__float2bfloat16_rn(v0));
        b1 = __bfloat16_as_ushort(__float2bfloat16_rn(v1));
    } else {
        b0 = __bfloat16_as_ushort(__float2bfloat16_rn(v0 - __bfloat162float(__float2bfloat16_rn(v0))));
        b1 = __bfloat16_as_ushort(__float2bfloat16_rn(v1 - __bfloat162float(__float2bfloat16_rn(v1))));
    }
    ((uint32_t*)g_Wfrag)[i] = (uint32_t)b0 | ((uint32_t)b1 << 16);
}

__device__ __forceinline__ uint32_t smem_u32(const void* p) {
    uint32_t a; asm("{ .reg .u64 t; cvta.to.shared.u64 t, %1; cvt.u32.u64 %0, t; }" : "=r"(a) : "l"(p));
    return a;
}
__device__ __forceinline__ uint32_t pkbf(float flo, float fhi) {
    uint32_t r; asm("cvt.rn.bf16x2.f32 %0, %1, %2;" : "=r"(r) : "f"(fhi), "f"(flo));
    return r;
}
__device__ __forceinline__ void ldm4(uint32_t* r, uint32_t addr) {
    asm volatile("ldmatrix.sync.aligned.m8n8.x4.shared.b16 {%0,%1,%2,%3}, [%4];"
        : "=r"(r[0]), "=r"(r[1]), "=r"(r[2]), "=r"(r[3]) : "r"(addr));
}
__device__ __forceinline__ void mma16816(float* c, const uint32_t* a, uint32_t b0, uint32_t b1) {
    asm volatile("mma.sync.aligned.m16n8k16.row.col.f32.bf16.bf16.f32 "
        "{%0,%1,%2,%3},{%4,%5,%6,%7},{%8,%9},{%0,%1,%2,%3};"
        : "+f"(c[0]), "+f"(c[1]), "+f"(c[2]), "+f"(c[3])
        : "r"(a[0]), "r"(a[1]), "r"(a[2]), "r"(a[3]), "r"(b0), "r"(b1));
}
__device__ __forceinline__ void cp16(uint32_t dst, const void* src) {
    asm volatile("cp.async.cg.shared.global [%0], [%1], 16;" :: "r"(dst), "l"(src));
}

__global__ __launch_bounds__(512, 1) void sconv_kernel(
    const float* __restrict__ x, const int* __restrict__ adj, float* __restrict__ out)
{
    extern __shared__ unsigned char S[];
    const uint32_t sb = smem_u32(S);
    const int tid = threadIdx.x, lid = tid & 31, wid = tid >> 5;
    const int b  = blockIdx.x >> 7;
    const int n0 = (blockIdx.x & 127) << 7;       // 128 points per block
    const float* xb = x + (size_t)b * NN * CC;

    int* adjS = (int*)S;
    {
        int base = (b * NN + n0) * 17;
        #pragma unroll
        for (int i = 0; i < 4; i++) {
            int idx = tid + 512 * i;              // 2048 ints (skip self col 0)
            adjS[idx] = adj[base + (idx >> 4) * 17 + 1 + (idx & 15)];
        }
    }
    __syncthreads();

    const int p_ = tid >> 2, l = tid & 3;         // 4 lanes/point, 16 channels each

    auto gatherA = [&](int j) {
        int g = adjS[p_ * 16 + j];
        const float* src = xb + (size_t)g * CC + l * 16;
        uint32_t dst = sb + SM_STG + p_ * RS + l * 64;
        #pragma unroll
        for (int q = 0; q < 4; q++) cp16(dst + q * 16, src + q * 4);
    };
    auto buildP = [&](int j) {
        const float4* st = (const float4*)(S + SM_STG + p_ * RS + l * 64);
        const float4* cp_ = (const float4*)(xb + (size_t)(n0 + p_) * CC + l * 16);
        float d[16]; float ssq = 0.f;
        #pragma unroll
        for (int q = 0; q < 4; q++) {
            float4 nv = st[q], cv = cp_[q];
            d[4*q+0] = nv.x - cv.x; d[4*q+1] = nv.y - cv.y;
            d[4*q+2] = nv.z - cv.z; d[4*q+3] = nv.w - cv.w;
        }
        #pragma unroll
        for (int q = 0; q < 16; q++) ssq = fmaf(d[q], d[q], ssq);
        ssq += __shfl_xor_sync(0xffffffffu, ssq, 1);
        ssq += __shfl_xor_sync(0xffffffffu, ssq, 2);
        float s = rsqrtf(2.0f * ssq);
        uint32_t h[8], lo[8];
        #pragma unroll
        for (int q = 0; q < 8; q++) {
            float e = d[2*q] * s, od = d[2*q+1] * s;
            h[q] = pkbf(e, od);
            float hl = __uint_as_float(h[q] << 16);
            float hh = __uint_as_float(h[q] & 0xFFFF0000u);
            lo[q] = pkbf(e - hl, od - hh);
        }
        unsigned char* P = S + SM_P + (j & 1) * 34816 + p_ * RS + l * 32;
        ((uint4*)P)[0] = ((uint4*)h)[0];  ((uint4*)P)[1] = ((uint4*)h)[1];
        ((uint4*)(P + 128))[0] = ((uint4*)lo)[0]; ((uint4*)(P + 128))[1] = ((uint4*)lo)[1];
    };

    // warp tiles: 4 m-warps x 4 n-warps; per warp m32 x n32
    const int mi = wid & 3;
    const int nw = (wid >> 2) * 32;
    const int g8 = lid >> 3, r8 = lid & 7;
    const uint32_t boff = (uint32_t)((nw + r8 + 8 * (g8 >> 1)) * RS + (g8 & 1) * 16);

    float acc[32], mx[32];
    #pragma unroll
    for (int i = 0; i < 32; i++) mx[i] = 0.f;     // relu+max -> init 0

    // prologue
    gatherA(0);
    asm volatile("cp.async.commit_group;");
    asm volatile("cp.async.wait_group 0;" ::: "memory");
    buildP(0);
    __syncthreads();

    for (int j = 0; j < JJ; j++) {
        if (j + 1 < JJ) {
            gatherA(j + 1);
            asm volatile("cp.async.commit_group;");
        }
        #pragma unroll
        for (int i = 0; i < 32; i++) acc[i] = 0.f;
        const uint32_t Pb = sb + SM_P + (j & 1) * 34816;
        #pragma unroll
        for (int c = 0; c < 4; c++) {
            // A fragments via LDG.128 from fragment-layout global (L1-resident)
            const unsigned char* ab = g_Wfrag + ((size_t)((j * 4 + c) * 8 + mi) << 10) + (lid << 4);
            uint32_t ah[8], al[8];
            *(uint4*)(ah)     = *(const uint4*)(ab);
            *(uint4*)(ah + 4) = *(const uint4*)(ab + 512);
            *(uint4*)(al)     = *(const uint4*)(ab + 4096);
            *(uint4*)(al + 4) = *(const uint4*)(ab + 4608);
            // B fragments via ldmatrix from proj smem
            uint32_t bh[8], bl[8];
            ldm4(bh,     Pb + boff + 32 * c);
            ldm4(bh + 4, Pb + boff + 16 * RS + 32 * c);
            ldm4(bl,     Pb + boff + 128 + 32 * c);
            ldm4(bl + 4, Pb + boff + 16 * RS + 128 + 32 * c);
            // 3 cross terms: hi*hi + hi*lo + lo*hi
            #pragma unroll
            for (int q = 0; q < 2; q++) {
                #pragma unroll
                for (int h2 = 0; h2 < 2; h2++) {
                    int nt = 2 * q + h2;
                    uint32_t bhi0 = bh[4*q + 2*h2], bhi1 = bh[4*q + 2*h2 + 1];
                    uint32_t blo0 = bl[4*q + 2*h2], blo1 = bl[4*q + 2*h2 + 1];
                    mma16816(&acc[nt * 4],      ah,     bhi0, bhi1);
                    mma16816(&acc[16 + nt * 4], ah + 4, bhi0, bhi1);
                    mma16816(&acc[nt * 4],      ah,     blo0, blo1);
                    mma16816(&acc[16 + nt * 4], ah + 4, blo0, blo1);
                    mma16816(&acc[nt * 4],      al,     bhi0, bhi1);
                    mma16816(&acc[16 + nt * 4], al + 4, bhi0, bhi1);
                }
            }
        }
        #pragma unroll
        for (int i = 0; i < 32; i++) mx[i] = fmaxf(mx[i], acc[i]);

        if (j + 1 < JJ) {
            asm volatile("cp.async.wait_group 0;" ::: "memory");
            buildP(j + 1);
        }
        __syncthreads();
    }

    // write out[b][o][n]
    {
        const int r4 = lid >> 2, c4 = lid & 3;
        const int m0 = mi * 32;
        #pragma unroll
        for (int mh = 0; mh < 2; mh++) {
            #pragma unroll
            for (int nt = 0; nt < 4; nt++) {
                float* a = &mx[mh * 16 + nt * 4];
                int ncol = n0 + nw + nt * 8 + 2 * c4;
                int o1 = m0 + 16 * mh + r4;
                *(float2*)(out + (size_t)(b * OO + o1) * NN + ncol)     = make_float2(a[0], a[1]);
                *(float2*)(out + (size_t)(b * OO + o1 + 8) * NN + ncol) = make_float2(a[2], a[3]);
            }
        }
    }
}

extern "C" void kernel_launch(void* const* d_in, const int* in_sizes, int n_in,
                              void* d_out, int out_size) {
    const float* x   = (const float*)d_in[0];
    const int*   adj = (const int*)d_in[1];
    const float* w   = (const float*)d_in[2];
    float* out = (float*)d_out;

    cudaFuncSetAttribute(sconv_kernel, cudaFuncAttributeMaxDynamicSharedMemorySize, SMEMTOT);
    wprep<<<512, 256>>>(w);
    sconv_kernel<<<256, 512, SMEMTOT>>>(x, adj, out);
}

// round 8
// speedup vs baseline: 4.1180x; 1.1058x over previous
#include <cuda_runtime.h>
#include <cuda_bf16.h>
#include <cstdint>

#define NN 16384
#define CC 64
#define JJ 16
#define OO 128
#define RS 272                 // proj smem row stride bytes (256 data + 16 pad)
#define PB 17408               // per proj buffer: 64 points * RS

// smem layout (bytes)
#define SM_ADJ 0               // 64*16*4 = 4096
#define SM_P   4096            // 2 x 17408
#define SM_STG (4096 + 2*PB)   // 38912; 17408 gather staging
#define SMEMTOT (38912 + PB)   // 56320

// W pre-baked in mma-fragment layout:
// byte addr = (((j*4+chunk)*2+seg)*4 + mi)*1024 + half*512 + lane*16 + word*4
__device__ unsigned char g_Wfrag[JJ * 4 * 2 * 4 * 1024];   // 512 KB

__global__ void wprep(const float* __restrict__ w) {
    int i = blockIdx.x * 256 + threadIdx.x;      // 131072 words
    int wrd  = i & 3;
    int lane = (i >> 2) & 31;
    int half = (i >> 7) & 1;
    int mi   = (i >> 8) & 3;
    int seg  = (i >> 10) & 1;
    int chunk= (i >> 11) & 3;
    int j    = i >> 13;
    int o = mi * 32 + half * 16 + (wrd & 1) * 8 + (lane >> 2);
    int k = chunk * 16 + ((wrd >> 1) & 1) * 8 + 2 * (lane & 3);
    float v0 = w[(o * CC + k) * JJ + j];
    float v1 = w[(o * CC + k + 1) * JJ + j];
    unsigned short b0, b1;
    if (seg == 0) {
        b0 = __bfloat16_as_ushort(__float2bfloat16_rn(v0));
        b1 = __bfloat16_as_ushort(__float2bfloat16_rn(v1));
    } else {
        b0 = __bfloat16_as_ushort(__float2bfloat16_rn(v0 - __bfloat162float(__float2bfloat16_rn(v0))));
        b1 = __bfloat16_as_ushort(__float2bfloat16_rn(v1 - __bfloat162float(__float2bfloat16_rn(v1))));
    }
    ((uint32_t*)g_Wfrag)[i] = (uint32_t)b0 | ((uint32_t)b1 << 16);
}

__device__ __forceinline__ uint32_t smem_u32(const void* p) {
    uint32_t a; asm("{ .reg .u64 t; cvta.to.shared.u64 t, %1; cvt.u32.u64 %0, t; }" : "=r"(a) : "l"(p));
    return a;
}
__device__ __forceinline__ uint32_t pkbf(float flo, float fhi) {
    uint32_t r; asm("cvt.rn.bf16x2.f32 %0, %1, %2;" : "=r"(r) : "f"(fhi), "f"(flo));
    return r;
}
__device__ __forceinline__ void ldm4(uint32_t* r, uint32_t addr) {
    asm volatile("ldmatrix.sync.aligned.m8n8.x4.shared.b16 {%0,%1,%2,%3}, [%4];"
        : "=r"(r[0]), "=r"(r[1]), "=r"(r[2]), "=r"(r[3]) : "r"(addr));
}
__device__ __forceinline__ void mma16816(float* c, const uint32_t* a, uint32_t b0, uint32_t b1) {
    asm volatile("mma.sync.aligned.m16n8k16.row.col.f32.bf16.bf16.f32 "
        "{%0,%1,%2,%3},{%4,%5,%6,%7},{%8,%9},{%0,%1,%2,%3};"
        : "+f"(c[0]), "+f"(c[1]), "+f"(c[2]), "+f"(c[3])
        : "r"(a[0]), "r"(a[1]), "r"(a[2]), "r"(a[3]), "r"(b0), "r"(b1));
}
__device__ __forceinline__ void cp16(uint32_t dst, const void* src) {
    asm volatile("cp.async.cg.shared.global [%0], [%1], 16;" :: "r"(dst), "l"(src));
}

__global__ __launch_bounds__(256, 2) void sconv_kernel(
    const float* __restrict__ x, const int* __restrict__ adj, float* __restrict__ out)
{
    extern __shared__ unsigned char S[];
    const uint32_t sb = smem_u32(S);
    const int tid = threadIdx.x, lid = tid & 31, wid = tid >> 5;
    const int b  = blockIdx.x >> 7;
    const int nbase = (blockIdx.x & 127) << 7;    // 128 points, 2 tiles of 64
    const float* xb = x + (size_t)b * NN * CC;

    const int p_ = tid >> 2, l = tid & 3;         // 4 lanes/point, 16 channels each

    // warp tiles: 4 m-warps x 2 n-warps; per warp m32 x n32
    const int mi = wid & 3;
    const int nw = (wid >> 2) * 32;
    const int g8 = lid >> 3, r8 = lid & 7;
    const uint32_t boff = (uint32_t)((nw + r8 + 8 * (g8 >> 1)) * RS + (g8 & 1) * 16);
    const int r4 = lid >> 2, c4 = lid & 3;

    int* adjS = (int*)S;

    for (int t = 0; t < 2; t++) {
        const int n0 = nbase + t * 64;

        // adjacency for this tile: 64*16 ints (skip self col 0)
        {
            int base = (b * NN + n0) * 17;
            #pragma unroll
            for (int i = 0; i < 4; i++) {
                int idx = tid + 256 * i;          // 1024 ints
                adjS[idx] = adj[base + (idx >> 4) * 17 + 1 + (idx & 15)];
            }
        }
        __syncthreads();

        auto gatherA = [&](int j) {
            int g = adjS[p_ * 16 + j];
            const float* src = xb + (size_t)g * CC + l * 16;
            uint32_t dst = sb + SM_STG + p_ * RS + l * 64;
            #pragma unroll
            for (int q = 0; q < 4; q++) cp16(dst + q * 16, src + q * 4);
        };
        auto buildP = [&](int j) {
            const float4* st = (const float4*)(S + SM_STG + p_ * RS + l * 64);
            const float4* cp_ = (const float4*)(xb + (size_t)(n0 + p_) * CC + l * 16);
            float d[16]; float ssq = 0.f;
            #pragma unroll
            for (int q = 0; q < 4; q++) {
                float4 nv = st[q], cv = cp_[q];
                d[4*q+0] = nv.x - cv.x; d[4*q+1] = nv.y - cv.y;
                d[4*q+2] = nv.z - cv.z; d[4*q+3] = nv.w - cv.w;
            }
            #pragma unroll
            for (int q = 0; q < 16; q++) ssq = fmaf(d[q], d[q], ssq);
            ssq += __shfl_xor_sync(0xffffffffu, ssq, 1);
            ssq += __shfl_xor_sync(0xffffffffu, ssq, 2);
            float s = rsqrtf(2.0f * ssq);
            uint32_t h[8], lo[8];
            #pragma unroll
            for (int q = 0; q < 8; q++) {
                float e = d[2*q] * s, od = d[2*q+1] * s;
                h[q] = pkbf(e, od);
                float hl = __uint_as_float(h[q] << 16);
                float hh = __uint_as_float(h[q] & 0xFFFF0000u);
                lo[q] = pkbf(e - hl, od - hh);
            }
            unsigned char* P = S + SM_P + (j & 1) * PB + p_ * RS + l * 32;
            ((uint4*)P)[0] = ((uint4*)h)[0];  ((uint4*)P)[1] = ((uint4*)h)[1];
            ((uint4*)(P + 128))[0] = ((uint4*)lo)[0]; ((uint4*)(P + 128))[1] = ((uint4*)lo)[1];
        };

        float acc[32], mx[32];
        #pragma unroll
        for (int i = 0; i < 32; i++) mx[i] = 0.f;

        gatherA(0);
        asm volatile("cp.async.commit_group;");
        asm volatile("cp.async.wait_group 0;" ::: "memory");
        buildP(0);
        __syncthreads();

        for (int j = 0; j < JJ; j++) {
            if (j + 1 < JJ) {
                gatherA(j + 1);
                asm volatile("cp.async.commit_group;");
            }
            #pragma unroll
            for (int i = 0; i < 32; i++) acc[i] = 0.f;
            const uint32_t Pb = sb + SM_P + (j & 1) * PB;
            #pragma unroll
            for (int c = 0; c < 4; c++) {
                const unsigned char* ab = g_Wfrag + ((size_t)((j * 4 + c) * 8 + mi) << 10) + (lid << 4);
                uint32_t ah[8], al[8];
                *(uint4*)(ah)     = *(const uint4*)(ab);
                *(uint4*)(ah + 4) = *(const uint4*)(ab + 512);
                *(uint4*)(al)     = *(const uint4*)(ab + 4096);
                *(uint4*)(al + 4) = *(const uint4*)(ab + 4608);
                uint32_t bh[8], bl[8];
                ldm4(bh,     Pb + boff + 32 * c);
                ldm4(bh + 4, Pb + boff + 16 * RS + 32 * c);
                ldm4(bl,     Pb + boff + 128 + 32 * c);
                ldm4(bl + 4, Pb + boff + 16 * RS + 128 + 32 * c);
                #pragma unroll
                for (int q = 0; q < 2; q++) {
                    #pragma unroll
                    for (int h2 = 0; h2 < 2; h2++) {
                        int nt = 2 * q + h2;
                        uint32_t bhi0 = bh[4*q + 2*h2], bhi1 = bh[4*q + 2*h2 + 1];
                        uint32_t blo0 = bl[4*q + 2*h2], blo1 = bl[4*q + 2*h2 + 1];
                        mma16816(&acc[nt * 4],      ah,     bhi0, bhi1);
                        mma16816(&acc[16 + nt * 4], ah + 4, bhi0, bhi1);
                        mma16816(&acc[nt * 4],      ah,     blo0, blo1);
                        mma16816(&acc[16 + nt * 4], ah + 4, blo0, blo1);
                        mma16816(&acc[nt * 4],      al,     bhi0, bhi1);
                        mma16816(&acc[16 + nt * 4], al + 4, bhi0, bhi1);
                    }
                }
            }
            #pragma unroll
            for (int i = 0; i < 32; i++) mx[i] = fmaxf(mx[i], acc[i]);

            if (j + 1 < JJ) {
                asm volatile("cp.async.wait_group 0;" ::: "memory");
                buildP(j + 1);
            }
            __syncthreads();
        }

        // write out[b][o][n]
        {
            const int m0 = mi * 32;
            #pragma unroll
            for (int mh = 0; mh < 2; mh++) {
                #pragma unroll
                for (int nt = 0; nt < 4; nt++) {
                    float* a = &mx[mh * 16 + nt * 4];
                    int ncol = n0 + nw + nt * 8 + 2 * c4;
                    int o1 = m0 + 16 * mh + r4;
                    *(float2*)(out + (size_t)(b * OO + o1) * NN + ncol)     = make_float2(a[0], a[1]);
                    *(float2*)(out + (size_t)(b * OO + o1 + 8) * NN + ncol) = make_float2(a[2], a[3]);
                }
            }
        }
        __syncthreads();   // adjS reuse safety for next tile
    }
}

extern "C" void kernel_launch(void* const* d_in, const int* in_sizes, int n_in,
                              void* d_out, int out_size) {
    const float* x   = (const float*)d_in[0];
    const int*   adj = (const int*)d_in[1];
    const float* w   = (const float*)d_in[2];
    float* out = (float*)d_out;

    cudaFuncSetAttribute(sconv_kernel, cudaFuncAttributeMaxDynamicSharedMemorySize, SMEMTOT);
    wprep<<<512, 256>>>(w);
    sconv_kernel<<<256, 256, SMEMTOT>>>(x, adj, out);
}